// round 6
// baseline (speedup 1.0000x reference)
#include <cuda_runtime.h>

// MemN2N on GB300 (sm_103a)
// B=128, M=200, S=20, D=128, V=100000, NC=10000, CL=10, 3 hops.
// Inputs: stories(i64), queries(i64), candidates(i64),
//         A_tab(f32 V*D), W_tab(f32 V*D), H_w(f32 D*D)
// Output: logits f32 [B, NC]
//
// 2-kernel pipeline, both at the LTS (L2->SM) bandwidth wall:
//  K1 k_hops:   per-b block gathers story embeddings DIRECTLY into smem
//               (no g_m global roundtrip), then runs 3 hops in smem.
//  K2 k_logits: gathers its 40 candidate sums into smem (no g_cs roundtrip),
//               then FFMA2 GEMM U[128,128] @ CS^T.

#define NB   128
#define NM   200
#define NS   20
#define ND   128
#define NCN  10000
#define NCL  10
#define TC   40     // candidates per k_logits block (250*40 == 10000 exactly)

__device__ float g_u[NB * ND];          // query state after hops (only global scratch)

__device__ __forceinline__ int detect64(const int* __restrict__ p) {
    // values < 100000: if int64 (LE), high words of first elements are 0.
    return (p[1] == 0 && p[3] == 0 && p[5] == 0 && p[7] == 0) ? 1 : 0;
}

// ---------------------------------------------------------------------------
// K1: one block (512 threads) per b. Gathers m[b] straight into smem,
// stages H, computes u0, runs 3 hops entirely in shared memory.
__global__ __launch_bounds__(512) void k_hops(const int* __restrict__ stories,
                                              const int* __restrict__ queries,
                                              const float4* __restrict__ A4,
                                              const float* __restrict__ Hw) {
    extern __shared__ float sm[];
    float* sm_m    = sm;                       // NM*ND = 25600 floats
    float* sm_H    = sm_m + NM * ND;           // 16384
    float* sm_u    = sm_H + ND * ND;           // 128
    float* sm_dot  = sm_u + ND;                // 200
    float* sm_prob = sm_dot + NM;              // 200
    float* sm_o    = sm_prob + NM;             // 256  [2][128] partials
    float* sm_hu   = sm_o + 2 * ND;            // 256  [2][128] partials
    float* sm_red  = sm_hu + 2 * ND;           // 64

    int b    = blockIdx.x;
    int tid  = threadIdx.x;
    int lane = tid & 31;
    int wid  = tid >> 5;     // 0..15

    // ---- gather phase: warp wid fills rows mm = wid + 16*t ----
    {
        int is64 = detect64(stories);
#pragma unroll
        for (int t = 0; t < 13; t++) {
            int mm = wid + 16 * t;
            if (mm < NM) {
                int idx[NS];
                if (is64) {
                    const int* p = stories + ((size_t)(b * NM + mm)) * NS * 2;
#pragma unroll
                    for (int s = 0; s < NS; s++) idx[s] = p[2 * s];
                } else {
                    const int* p = stories + ((size_t)(b * NM + mm)) * NS;
#pragma unroll
                    for (int s = 0; s < NS; s++) idx[s] = p[s];
                }
                float4 acc = make_float4(0.f, 0.f, 0.f, 0.f);
#pragma unroll
                for (int c0 = 0; c0 < NS; c0 += 5) {
                    float4 v[5];
#pragma unroll
                    for (int j = 0; j < 5; j++)
                        v[j] = A4[(size_t)idx[c0 + j] * 32 + lane];   // row 0 valid
#pragma unroll
                    for (int j = 0; j < 5; j++)
                        if (idx[c0 + j] != 0) {
                            acc.x += v[j].x; acc.y += v[j].y;
                            acc.z += v[j].z; acc.w += v[j].w;
                        }
                }
                reinterpret_cast<float4*>(sm_m)[mm * 32 + lane] = acc;
            }
        }
    }

    // ---- stage H (4096 float4) ----
    {
        const float4* H4 = reinterpret_cast<const float4*>(Hw);
        float4* smH4 = reinterpret_cast<float4*>(sm_H);
        for (int i = tid; i < 4096; i += 512) smH4[i] = H4[i];
    }

    // ---- u0 = sum_s A[queries[b][s]] : thread d ----
    if (tid < ND) {
        int is64 = detect64(queries);
        int idx[NS];
        if (is64) {
            const int* p = queries + (size_t)b * NS * 2;
#pragma unroll
            for (int s = 0; s < NS; s++) idx[s] = p[2 * s];
        } else {
            const int* p = queries + (size_t)b * NS;
#pragma unroll
            for (int s = 0; s < NS; s++) idx[s] = p[s];
        }
        const float* A = reinterpret_cast<const float*>(A4);
        float u = 0.f;
#pragma unroll
        for (int c0 = 0; c0 < NS; c0 += 5) {
            float v[5];
#pragma unroll
            for (int j = 0; j < 5; j++) v[j] = A[(size_t)idx[c0 + j] * ND + tid];
#pragma unroll
            for (int j = 0; j < 5; j++) if (idx[c0 + j] != 0) u += v[j];
        }
        sm_u[tid] = u;
    }
    __syncthreads();

    for (int hop = 0; hop < 3; hop++) {
        // dotted[mm] = dot(m[mm], u)
        float4 u4 = reinterpret_cast<float4*>(sm_u)[lane];
#pragma unroll
        for (int t = 0; t < 13; t++) {
            int mm = wid + 16 * t;
            if (mm < NM) {
                float4 mv = reinterpret_cast<float4*>(sm_m)[mm * 32 + lane];
                float d = mv.x * u4.x + mv.y * u4.y + mv.z * u4.z + mv.w * u4.w;
#pragma unroll
                for (int o = 16; o; o >>= 1) d += __shfl_xor_sync(0xffffffffu, d, o);
                if (lane == 0) sm_dot[mm] = d;
            }
        }
        __syncthreads();

        // softmax over 200 (16-warp block reduce)
        float v = (tid < NM) ? sm_dot[tid] : -1e30f;
        float r = v;
#pragma unroll
        for (int o = 16; o; o >>= 1) r = fmaxf(r, __shfl_xor_sync(0xffffffffu, r, o));
        if (lane == 0) sm_red[wid] = r;
        __syncthreads();
        if (tid < 32) {
            float rr = (tid < 16) ? sm_red[tid] : -1e30f;
#pragma unroll
            for (int o = 8; o; o >>= 1) rr = fmaxf(rr, __shfl_xor_sync(0xffffffffu, rr, o));
            if (tid == 0) sm_red[32] = rr;
        }
        __syncthreads();
        float mx = sm_red[32];
        float e = (tid < NM) ? __expf(v - mx) : 0.f;
        if (tid < NM) sm_prob[tid] = e;
        float s = e;
#pragma unroll
        for (int o = 16; o; o >>= 1) s += __shfl_xor_sync(0xffffffffu, s, o);
        if (lane == 0) sm_red[wid] = s;
        __syncthreads();
        if (tid < 32) {
            float ss = (tid < 16) ? sm_red[tid] : 0.f;
#pragma unroll
            for (int o = 8; o; o >>= 1) ss += __shfl_xor_sync(0xffffffffu, ss, o);
            if (tid == 0) sm_red[33] = ss;
        }
        __syncthreads();
        float inv = 1.0f / sm_red[33];

        // [0,256): o-partials over mm-halves; [256,512): Hu-partials, diag swizzle
        if (tid < 2 * ND) {
            int d = tid & (ND - 1), h = tid >> 7;
            float o = 0.f;
            int m0 = h * 100;
#pragma unroll 4
            for (int mm = m0; mm < m0 + 100; mm++) o += sm_prob[mm] * sm_m[mm * ND + d];
            sm_o[h * ND + d] = o;
        } else {
            int t2 = tid - 2 * ND;
            int d = t2 & (ND - 1), h = t2 >> 7;
            float hu = 0.f;
            int j0 = h * 64;
#pragma unroll 4
            for (int j = j0; j < j0 + 64; j++) {
                int dp = (d + j) & (ND - 1);
                hu += sm_H[d * ND + dp] * sm_u[dp];
            }
            sm_hu[h * ND + d] = hu;
        }
        __syncthreads();
        if (tid < ND)
            sm_u[tid] = tanhf(sm_hu[tid] + sm_hu[ND + tid]
                              + (sm_o[tid] + sm_o[ND + tid]) * inv);
        __syncthreads();
    }
    if (tid < ND) g_u[b * ND + tid] = sm_u[tid];
}

// ---------------------------------------------------------------------------
// K2: fused candidate gather + logits GEMM.
// grid 250, block 320, 2 CTAs/SM. Thread tile 4b x 4c; FFMA2 even/odd-k halves.
#define FFMA2(acc, a, b) \
    asm("fma.rn.f32x2 %0, %1, %2, %0;" : "+l"(acc) : "l"(a), "l"(b))

__device__ __forceinline__ float ul_sum(unsigned long long v) {
    float lo, hi;
    asm("mov.b64 {%0,%1}, %2;" : "=f"(lo), "=f"(hi) : "l"(v));
    return lo + hi;
}

__global__ __launch_bounds__(320, 2) void k_logits(const int* __restrict__ cand,
                                                   const float4* __restrict__ W4,
                                                   float* __restrict__ out) {
    extern __shared__ float sm[];
    float* sm_u  = sm;                 // [128][132] padded, conflict-free LDS.128
    float* sm_cs = sm + NB * 132;      // [40][132]; reused as [128][41] transpose buf
    int tid  = threadIdx.x;
    int lane = tid & 31;
    int wid  = tid >> 5;               // 0..9
    int c0   = blockIdx.x * TC;

    // stage u (4096 float4)
    for (int i = tid; i < NB * 32; i += 320) {
        int bb = i >> 5, q = i & 31;
        *reinterpret_cast<float4*>(sm_u + bb * 132 + q * 4) =
            reinterpret_cast<const float4*>(g_u)[i];
    }

    // candidate sums: warp wid computes cands wid*4 .. wid*4+3 (40 total)
    {
        int is64 = detect64(cand);
#pragma unroll
        for (int j = 0; j < 4; j++) {
            int cl = wid * 4 + j;
            int c  = c0 + cl;          // < 10000 by construction (250*40)
            int idx[NCL];
            if (is64) {
                const int* p = cand + (size_t)c * NCL * 2;
#pragma unroll
                for (int l = 0; l < NCL; l++) idx[l] = p[2 * l];
            } else {
                const int* p = cand + (size_t)c * NCL;
#pragma unroll
                for (int l = 0; l < NCL; l++) idx[l] = p[l];
            }
            float4 acc = make_float4(0.f, 0.f, 0.f, 0.f);
#pragma unroll
            for (int l0 = 0; l0 < NCL; l0 += 5) {
                float4 v[5];
#pragma unroll
                for (int jj = 0; jj < 5; jj++)
                    v[jj] = W4[(size_t)idx[l0 + jj] * 32 + lane];
#pragma unroll
                for (int jj = 0; jj < 5; jj++)
                    if (idx[l0 + jj] != 0) {
                        acc.x += v[jj].x; acc.y += v[jj].y;
                        acc.z += v[jj].z; acc.w += v[jj].w;
                    }
            }
            *reinterpret_cast<float4*>(sm_cs + cl * 132 + lane * 4) = acc;
        }
    }
    __syncthreads();

    unsigned long long acc[4][4];
#pragma unroll
    for (int jb = 0; jb < 4; jb++)
#pragma unroll
        for (int jc = 0; jc < 4; jc++) acc[jb][jc] = 0ull;

#pragma unroll 8
    for (int k4 = 0; k4 < 32; k4++) {
        ulonglong2 uq[4], cq[4];
#pragma unroll
        for (int jb = 0; jb < 4; jb++)
            uq[jb] = *reinterpret_cast<const ulonglong2*>(sm_u + (lane + 32 * jb) * 132 + k4 * 4);
#pragma unroll
        for (int jc = 0; jc < 4; jc++)
            cq[jc] = *reinterpret_cast<const ulonglong2*>(sm_cs + (wid * 4 + jc) * 132 + k4 * 4);
#pragma unroll
        for (int jb = 0; jb < 4; jb++)
#pragma unroll
            for (int jc = 0; jc < 4; jc++) {
                FFMA2(acc[jb][jc], uq[jb].x, cq[jc].x);
                FFMA2(acc[jb][jc], uq[jb].y, cq[jc].y);
            }
    }

    // transpose through smem for coalesced stores
    __syncthreads();
#pragma unroll
    for (int jb = 0; jb < 4; jb++)
#pragma unroll
        for (int jc = 0; jc < 4; jc++)
            sm_cs[(lane + 32 * jb) * 41 + (wid * 4 + jc)] = ul_sum(acc[jb][jc]);
    __syncthreads();
    for (int i = tid; i < NB * TC; i += 320) {
        int bb = i / TC, cl = i % TC;
        out[(size_t)bb * NCN + c0 + cl] = sm_cs[bb * 41 + cl];
    }
}

// ---------------------------------------------------------------------------
extern "C" void kernel_launch(void* const* d_in, const int* in_sizes, int n_in,
                              void* d_out, int out_size) {
    const int*    stories = (const int*)d_in[0];
    const int*    queries = (const int*)d_in[1];
    const int*    cand    = (const int*)d_in[2];
    const float*  A_tab   = (const float*)d_in[3];
    const float*  W_tab   = (const float*)d_in[4];
    const float*  H_w     = (const float*)d_in[5];
    float* out = (float*)d_out;

    const int hops_smem   = (NM * ND + ND * ND + ND + NM + NM + 2 * ND + 2 * ND + 64) * 4; // 172352 B
    const int logits_smem = (NB * 132 + TC * 132) * 4;                                     // 88704 B
    cudaFuncSetAttribute(k_hops,   cudaFuncAttributeMaxDynamicSharedMemorySize, hops_smem);
    cudaFuncSetAttribute(k_logits, cudaFuncAttributeMaxDynamicSharedMemorySize, logits_smem);

    k_hops<<<NB, 512, hops_smem>>>(stories, queries, (const float4*)A_tab, H_w);
    k_logits<<<NCN / TC, 320, logits_smem>>>(cand, (const float4*)W_tab, out);
}

// round 7
// speedup vs baseline: 1.0988x; 1.0988x over previous
#include <cuda_runtime.h>

// MemN2N on GB300 (sm_103a)
// B=128, M=200, S=20, D=128, V=100000, NC=10000, CL=10, 3 hops.
// Inputs: stories(i64), queries(i64), candidates(i64),
//         A_tab(f32 V*D), W_tab(f32 V*D), H_w(f32 D*D)
// Output: logits f32 [B, NC]
//
// K1 k_gather: story gathers at max occupancy -> g_m (LTS-cap bound, ~23.5us)
// K2 k_hops:   per-b block streams g_m into smem, 3 hops in smem
// K3 k_logits: fused candidate gather + FFMA2 GEMM, 2b x 8c thread tile

#define NB   128
#define NM   200
#define NS   20
#define ND   128
#define NCN  10000
#define NCL  10
#define TC   40     // candidates per k_logits block (250*40 == 10000 exactly)

__device__ float g_m[NB * NM * ND];     // 13.1 MB memory encodings
__device__ float g_u[NB * ND];          // query state after hops

__device__ __forceinline__ int detect64(const int* __restrict__ p) {
    // values < 100000: if int64 (LE), high words of first elements are 0.
    return (p[1] == 0 && p[3] == 0 && p[5] == 0 && p[7] == 0) ? 1 : 0;
}

// ---------------------------------------------------------------------------
// K1: story gathers. Warp w -> m[w][:] = sum_s A[stories[w][s]].
// 3200 blocks * 8 warps = 25600 warps. Indices preloaded, gathers batched
// (row 0 valid memory), accumulate predicated on idx!=0.
__global__ __launch_bounds__(256) void k_gather(const int* __restrict__ stories,
                                                const float4* __restrict__ A4) {
    int w    = blockIdx.x * 8 + (threadIdx.x >> 5);
    int lane = threadIdx.x & 31;
    int is64 = detect64(stories);
    int idx[NS];
    if (is64) {
        const int* p = stories + (size_t)w * NS * 2;
#pragma unroll
        for (int s = 0; s < NS; s++) idx[s] = p[2 * s];
    } else {
        const int* p = stories + (size_t)w * NS;
#pragma unroll
        for (int s = 0; s < NS; s++) idx[s] = p[s];
    }
    float4 acc = make_float4(0.f, 0.f, 0.f, 0.f);
#pragma unroll
    for (int c0 = 0; c0 < NS; c0 += 5) {
        float4 v[5];
#pragma unroll
        for (int j = 0; j < 5; j++)
            v[j] = A4[(size_t)idx[c0 + j] * 32 + lane];
#pragma unroll
        for (int j = 0; j < 5; j++)
            if (idx[c0 + j] != 0) {
                acc.x += v[j].x; acc.y += v[j].y;
                acc.z += v[j].z; acc.w += v[j].w;
            }
    }
    reinterpret_cast<float4*>(g_m)[(size_t)w * 32 + lane] = acc;
}

// ---------------------------------------------------------------------------
// K2: one block (512 threads) per b. Streams m[b] + H into smem, 3 hops.
__global__ __launch_bounds__(512) void k_hops(const int* __restrict__ queries,
                                              const float* __restrict__ A,
                                              const float* __restrict__ Hw) {
    extern __shared__ float sm[];
    float* sm_m    = sm;                       // NM*ND = 25600 floats
    float* sm_H    = sm_m + NM * ND;           // 16384
    float* sm_u    = sm_H + ND * ND;           // 128
    float* sm_dot  = sm_u + ND;                // 200
    float* sm_prob = sm_dot + NM;              // 200
    float* sm_o    = sm_prob + NM;             // 256  [2][128] partials
    float* sm_hu   = sm_o + 2 * ND;            // 256  [2][128] partials
    float* sm_red  = sm_hu + 2 * ND;           // 64

    int b    = blockIdx.x;
    int tid  = threadIdx.x;
    int lane = tid & 31;
    int wid  = tid >> 5;     // 0..15

    const float4* gm4 = reinterpret_cast<const float4*>(g_m) + (size_t)b * NM * 32;
    float4* smm4 = reinterpret_cast<float4*>(sm_m);
    for (int i = tid; i < NM * 32; i += 512) smm4[i] = gm4[i];
    const float4* H4 = reinterpret_cast<const float4*>(Hw);
    float4* smH4 = reinterpret_cast<float4*>(sm_H);
    for (int i = tid; i < 4096; i += 512) smH4[i] = H4[i];

    if (tid < ND) {
        int is64 = detect64(queries);
        int idx[NS];
        if (is64) {
            const int* p = queries + (size_t)b * NS * 2;
#pragma unroll
            for (int s = 0; s < NS; s++) idx[s] = p[2 * s];
        } else {
            const int* p = queries + (size_t)b * NS;
#pragma unroll
            for (int s = 0; s < NS; s++) idx[s] = p[s];
        }
        float u = 0.f;
#pragma unroll
        for (int c0 = 0; c0 < NS; c0 += 5) {
            float v[5];
#pragma unroll
            for (int j = 0; j < 5; j++) v[j] = A[(size_t)idx[c0 + j] * ND + tid];
#pragma unroll
            for (int j = 0; j < 5; j++) if (idx[c0 + j] != 0) u += v[j];
        }
        sm_u[tid] = u;
    }
    __syncthreads();

    for (int hop = 0; hop < 3; hop++) {
        // dotted[mm] = dot(m[mm], u)
        float4 u4 = reinterpret_cast<float4*>(sm_u)[lane];
#pragma unroll
        for (int t = 0; t < 13; t++) {
            int mm = wid + 16 * t;
            if (mm < NM) {
                float4 mv = reinterpret_cast<float4*>(sm_m)[mm * 32 + lane];
                float d = mv.x * u4.x + mv.y * u4.y + mv.z * u4.z + mv.w * u4.w;
#pragma unroll
                for (int o = 16; o; o >>= 1) d += __shfl_xor_sync(0xffffffffu, d, o);
                if (lane == 0) sm_dot[mm] = d;
            }
        }
        __syncthreads();

        // softmax over 200 (16-warp block reduce)
        float v = (tid < NM) ? sm_dot[tid] : -1e30f;
        float r = v;
#pragma unroll
        for (int o = 16; o; o >>= 1) r = fmaxf(r, __shfl_xor_sync(0xffffffffu, r, o));
        if (lane == 0) sm_red[wid] = r;
        __syncthreads();
        if (tid < 32) {
            float rr = (tid < 16) ? sm_red[tid] : -1e30f;
#pragma unroll
            for (int o = 8; o; o >>= 1) rr = fmaxf(rr, __shfl_xor_sync(0xffffffffu, rr, o));
            if (tid == 0) sm_red[32] = rr;
        }
        __syncthreads();
        float mx = sm_red[32];
        float e = (tid < NM) ? __expf(v - mx) : 0.f;
        if (tid < NM) sm_prob[tid] = e;
        float s = e;
#pragma unroll
        for (int o = 16; o; o >>= 1) s += __shfl_xor_sync(0xffffffffu, s, o);
        if (lane == 0) sm_red[wid] = s;
        __syncthreads();
        if (tid < 32) {
            float ss = (tid < 16) ? sm_red[tid] : 0.f;
#pragma unroll
            for (int o = 8; o; o >>= 1) ss += __shfl_xor_sync(0xffffffffu, ss, o);
            if (tid == 0) sm_red[33] = ss;
        }
        __syncthreads();
        float inv = 1.0f / sm_red[33];

        // [0,256): o-partials over mm-halves; [256,512): Hu-partials, diag swizzle
        if (tid < 2 * ND) {
            int d = tid & (ND - 1), h = tid >> 7;
            float o = 0.f;
            int m0 = h * 100;
#pragma unroll 4
            for (int mm = m0; mm < m0 + 100; mm++) o += sm_prob[mm] * sm_m[mm * ND + d];
            sm_o[h * ND + d] = o;
        } else {
            int t2 = tid - 2 * ND;
            int d = t2 & (ND - 1), h = t2 >> 7;
            float hu = 0.f;
            int j0 = h * 64;
#pragma unroll 4
            for (int j = j0; j < j0 + 64; j++) {
                int dp = (d + j) & (ND - 1);
                hu += sm_H[d * ND + dp] * sm_u[dp];
            }
            sm_hu[h * ND + d] = hu;
        }
        __syncthreads();
        if (tid < ND)
            sm_u[tid] = tanhf(sm_hu[tid] + sm_hu[ND + tid]
                              + (sm_o[tid] + sm_o[ND + tid]) * inv);
        __syncthreads();
    }
    if (tid < ND) g_u[b * ND + tid] = sm_u[tid];
}

// ---------------------------------------------------------------------------
// K3: fused candidate gather + logits GEMM.
// grid 250, block 320, 2 CTAs/SM. Warp = (b-half bh, c-group cg): bh=wid&1,
// cg=wid>>1. Thread tile 2b x 8c; per k4-iter: 2 vector LDS.128 + 8 broadcast
// LDS.128 feed 64 FFMA2 lanes-pairs -> crossbar ~= FMA floor.
#define FFMA2(acc, a, b) \
    asm("fma.rn.f32x2 %0, %1, %2, %0;" : "+l"(acc) : "l"(a), "l"(b))

__device__ __forceinline__ float ul_sum(unsigned long long v) {
    float lo, hi;
    asm("mov.b64 {%0,%1}, %2;" : "=f"(lo), "=f"(hi) : "l"(v));
    return lo + hi;
}

__global__ __launch_bounds__(320, 2) void k_logits(const int* __restrict__ cand,
                                                   const float4* __restrict__ W4,
                                                   float* __restrict__ out) {
    extern __shared__ float sm[];
    float* sm_u  = sm;                 // [128][132] padded, conflict-free LDS.128
    float* sm_cs = sm + NB * 132;      // [40][132]; reused as [128][41] transpose buf
    int tid  = threadIdx.x;
    int lane = tid & 31;
    int wid  = tid >> 5;               // 0..9
    int c0   = blockIdx.x * TC;

    // stage u (4096 float4)
    for (int i = tid; i < NB * 32; i += 320) {
        int bb = i >> 5, q = i & 31;
        *reinterpret_cast<float4*>(sm_u + bb * 132 + q * 4) =
            reinterpret_cast<const float4*>(g_u)[i];
    }

    // candidate sums: warp wid computes cands wid*4 .. wid*4+3 (40 total)
    {
        int is64 = detect64(cand);
#pragma unroll
        for (int j = 0; j < 4; j++) {
            int cl = wid * 4 + j;
            int c  = c0 + cl;          // < 10000 by construction (250*40)
            int idx[NCL];
            if (is64) {
                const int* p = cand + (size_t)c * NCL * 2;
#pragma unroll
                for (int l = 0; l < NCL; l++) idx[l] = p[2 * l];
            } else {
                const int* p = cand + (size_t)c * NCL;
#pragma unroll
                for (int l = 0; l < NCL; l++) idx[l] = p[l];
            }
            float4 acc = make_float4(0.f, 0.f, 0.f, 0.f);
#pragma unroll
            for (int l0 = 0; l0 < NCL; l0 += 5) {
                float4 v[5];
#pragma unroll
                for (int jj = 0; jj < 5; jj++)
                    v[jj] = W4[(size_t)idx[l0 + jj] * 32 + lane];
#pragma unroll
                for (int jj = 0; jj < 5; jj++)
                    if (idx[l0 + jj] != 0) {
                        acc.x += v[jj].x; acc.y += v[jj].y;
                        acc.z += v[jj].z; acc.w += v[jj].w;
                    }
            }
            *reinterpret_cast<float4*>(sm_cs + cl * 132 + lane * 4) = acc;
        }
    }
    __syncthreads();

    int bh = wid & 1;          // b-half
    int cg = wid >> 1;         // c-group 0..4
    const float* csb = sm_cs + (cg * 8) * 132;
    const float* ub  = sm_u + (lane + 64 * bh) * 132;

    unsigned long long acc[2][8];
#pragma unroll
    for (int jb = 0; jb < 2; jb++)
#pragma unroll
        for (int jc = 0; jc < 8; jc++) acc[jb][jc] = 0ull;

#pragma unroll 8
    for (int k4 = 0; k4 < 32; k4++) {
        ulonglong2 uq[2];
#pragma unroll
        for (int jb = 0; jb < 2; jb++)
            uq[jb] = *reinterpret_cast<const ulonglong2*>(ub + jb * 32 * 132 + k4 * 4);
#pragma unroll
        for (int jc = 0; jc < 8; jc++) {
            ulonglong2 cq = *reinterpret_cast<const ulonglong2*>(csb + jc * 132 + k4 * 4);
            FFMA2(acc[0][jc], uq[0].x, cq.x);
            FFMA2(acc[0][jc], uq[0].y, cq.y);
            FFMA2(acc[1][jc], uq[1].x, cq.x);
            FFMA2(acc[1][jc], uq[1].y, cq.y);
        }
    }

    // transpose through smem for coalesced stores (reuse cs region)
    __syncthreads();
#pragma unroll
    for (int jb = 0; jb < 2; jb++)
#pragma unroll
        for (int jc = 0; jc < 8; jc++)
            sm_cs[(lane + 64 * bh + 32 * jb) * 41 + (cg * 8 + jc)] = ul_sum(acc[jb][jc]);
    __syncthreads();
    for (int i = tid; i < NB * TC; i += 320) {
        int bb = i / TC, cl = i % TC;
        out[(size_t)bb * NCN + c0 + cl] = sm_cs[bb * 41 + cl];
    }
}

// ---------------------------------------------------------------------------
extern "C" void kernel_launch(void* const* d_in, const int* in_sizes, int n_in,
                              void* d_out, int out_size) {
    const int*    stories = (const int*)d_in[0];
    const int*    queries = (const int*)d_in[1];
    const int*    cand    = (const int*)d_in[2];
    const float*  A_tab   = (const float*)d_in[3];
    const float*  W_tab   = (const float*)d_in[4];
    const float*  H_w     = (const float*)d_in[5];
    float* out = (float*)d_out;

    const int hops_smem   = (NM * ND + ND * ND + ND + NM + NM + 2 * ND + 2 * ND + 64) * 4; // 172352 B
    const int logits_smem = (NB * 132 + TC * 132) * 4;                                     // 88704 B
    cudaFuncSetAttribute(k_hops,   cudaFuncAttributeMaxDynamicSharedMemorySize, hops_smem);
    cudaFuncSetAttribute(k_logits, cudaFuncAttributeMaxDynamicSharedMemorySize, logits_smem);

    k_gather<<<(NB * NM) / 8, 256>>>(stories, (const float4*)A_tab);
    k_hops<<<NB, 512, hops_smem>>>(queries, A_tab, H_w);
    k_logits<<<NCN / TC, 320, logits_smem>>>(cand, (const float4*)W_tab, out);
}